// round 14
// baseline (speedup 1.0000x reference)
#include <cuda_runtime.h>
#include <cuda_fp16.h>
#include <math_constants.h>
#include <cstdint>

// Problem constants
#define BB   8
#define NN   1024
#define FIN  256
#define OUTD 256
#define DD   4
#define MTOT (BB * NN)   // 8192

// ---------------- scratch (static device globals; no dynamic alloc) ----------------
__device__ float g_wsrc[DD * FIN];
__device__ float g_wdst[DD * FIN];
__device__ float g_esrc[DD * MTOT];
__device__ float g_edst[DD * MTOT];
__device__ __align__(16) unsigned char g_Apack[NN * NN];              // 1 MB
__device__ __align__(16) uint4 g_Abits[NN * 32];                      // 0.5 MB bit-planes
__device__ __align__(16) __half g_al[(size_t)MTOT * NN];              // 16 MB alpha (fp16)
__device__ __align__(16) __half g_xh[(size_t)MTOT * FIN];             // 4 MB  x fp16 [b][j][f]
__device__ __align__(16) __half g_yt[(size_t)DD * BB * OUTD * NN];    // 16 MB [d][b][o][j]
__device__ __align__(16) __half g_wt[OUTD * 1024];                    // 0.5 MB [o][d*256+f]

// ---------------- helpers ----------------
__device__ __forceinline__ uint32_t smem_u32(const void* p) {
    uint32_t a;
    asm("{ .reg .u64 t; cvta.to.shared.u64 t, %1; cvt.u32.u64 %0, t; }" : "=r"(a) : "l"(p));
    return a;
}
__device__ __forceinline__ float warpSum(float v) {
    #pragma unroll
    for (int o = 16; o; o >>= 1) v += __shfl_xor_sync(0xffffffffu, v, o);
    return v;
}
// expand 2 adjacency bits -> per-half 0xFFFF masks
__device__ __forceinline__ uint32_t expand2(uint32_t b) {
    return (0xFFFFu & (0u - (b & 1u))) | (0xFFFF0000u & (0u - (b >> 1)));
}

#define LDSM_X4(r0, r1, r2, r3, addr)                                           \
    asm volatile("ldmatrix.sync.aligned.m8n8.x4.shared.b16 {%0,%1,%2,%3}, [%4];"\
                 : "=r"(r0), "=r"(r1), "=r"(r2), "=r"(r3) : "r"(addr))

#define CP16(dst, src)                                                          \
    asm volatile("cp.async.cg.shared.global [%0], [%1], 16;"                    \
                 :: "r"(dst), "l"(src))
#define CP_COMMIT() asm volatile("cp.async.commit_group;" ::: "memory")
#define CP_WAIT1()  asm volatile("cp.async.wait_group 1;" ::: "memory")
#define CP_WAIT0()  asm volatile("cp.async.wait_group 0;" ::: "memory")

__device__ __forceinline__ void mma16816(float c[4], const uint32_t a[4],
                                         uint32_t b0, uint32_t b1) {
    asm volatile(
        "mma.sync.aligned.m16n8k16.row.col.f32.f16.f16.f32 "
        "{%0,%1,%2,%3}, {%4,%5,%6,%7}, {%8,%9}, {%0,%1,%2,%3};"
        : "+f"(c[0]), "+f"(c[1]), "+f"(c[2]), "+f"(c[3])
        : "r"(a[0]), "r"(a[1]), "r"(a[2]), "r"(a[3]), "r"(b0), "r"(b1));
}

// ---------------- prep: w_src/w_dst (head 1) + Wt = transposed fp16 Wsum ----------------
__global__ void prep_kernel(const float* __restrict__ W, const float* __restrict__ a) {
    int d = blockIdx.x >> 8;
    int f = blockIdx.x & 255;
    int o = threadIdx.x;

    float w0 = W[((size_t)(d * 2 + 0) * FIN + f) * OUTD + o];
    float w1 = W[((size_t)(d * 2 + 1) * FIN + f) * OUTD + o];
    float wsum = w0 + w1;
    size_t wo = (size_t)o * 1024 + d * 256 + f;   // [o][d*256+f]
    g_wt[wo] = __float2half_rn(wsum);

    float a_s = a[(d * 2 + 1) * (2 * OUTD) + o];
    float a_d = a[(d * 2 + 1) * (2 * OUTD) + OUTD + o];
    float s1 = warpSum(w1 * a_s);
    float s2 = warpSum(w1 * a_d);
    __shared__ float r1[8], r2[8];
    int lane = threadIdx.x & 31, wid = threadIdx.x >> 5;
    if (lane == 0) { r1[wid] = s1; r2[wid] = s2; }
    __syncthreads();
    if (threadIdx.x == 0) {
        float t1 = 0.f, t2 = 0.f;
        #pragma unroll
        for (int w = 0; w < 8; w++) { t1 += r1[w]; t2 += r2[w]; }
        g_wsrc[d * FIN + f] = t1;
        g_wdst[d * FIN + f] = t2;
    }
}

// ---------------- fused adjacency pack + bit-planes ----------------
// thread handles (i, j32): 32 columns. Writes 32 Apack bytes + one uint4 of bit-planes.
__global__ void adj_kernel(const int* __restrict__ AU, const int* __restrict__ AD,
                           const int* __restrict__ AR, const int* __restrict__ AL) {
    int idx = blockIdx.x * 256 + threadIdx.x;  // 32768 = 1024 * 32
    int i = idx >> 5, j32 = idx & 31;
    size_t base = (size_t)i * NN + j32 * 32;
    unsigned w[4] = {0, 0, 0, 0};
    unsigned* pk = (unsigned*)(g_Apack + base);
    #pragma unroll
    for (int q8 = 0; q8 < 8; q8++) {
        unsigned word = 0;
        #pragma unroll
        for (int e = 0; e < 4; e++) {
            int q = q8 * 4 + e;
            unsigned m = (AU[base + q] != 0 ? 1u : 0u) | (AD[base + q] != 0 ? 2u : 0u) |
                         (AR[base + q] != 0 ? 4u : 0u) | (AL[base + q] != 0 ? 8u : 0u);
            word |= m << (8 * e);
            #pragma unroll
            for (int d = 0; d < 4; d++)
                w[d] |= ((m >> d) & 1u) << q;
        }
        pk[q8] = word;
    }
    g_Abits[idx] = make_uint4(w[0], w[1], w[2], w[3]);
}

// ---------------- x cast to fp16 (natural layout [b][j][f]) ----------------
__global__ void cast_kernel(const float* __restrict__ x) {
    int idx = blockIdx.x * 256 + threadIdx.x;   // over 2M/4 float4s
    float4 v = *(const float4*)(x + (size_t)idx * 4);
    unsigned p0 = (unsigned)__half_as_ushort(__float2half_rn(v.x)) |
                  ((unsigned)__half_as_ushort(__float2half_rn(v.y)) << 16);
    unsigned p1 = (unsigned)__half_as_ushort(__float2half_rn(v.z)) |
                  ((unsigned)__half_as_ushort(__float2half_rn(v.w)) << 16);
    *(uint2*)(g_xh + (size_t)idx * 4) = make_uint2(p0, p1);
}

// ---------------- e_src/e_dst: one warp per m, all 4 directions ----------------
__global__ void edge_kernel(const float* __restrict__ x) {
    int wid = threadIdx.x >> 5, lane = threadIdx.x & 31;
    int m = blockIdx.x * 8 + wid;
    const float* xr = x + (size_t)m * FIN;
    float xv[8];
    #pragma unroll
    for (int it = 0; it < 8; it++) xv[it] = xr[lane + 32 * it];
    #pragma unroll
    for (int d = 0; d < DD; d++) {
        float s1 = 0.f, s2 = 0.f;
        #pragma unroll
        for (int it = 0; it < 8; it++) {
            int k = lane + 32 * it;
            s1 += xv[it] * g_wsrc[d * FIN + k];
            s2 += xv[it] * g_wdst[d * FIN + k];
        }
        s1 = warpSum(s1);
        s2 = warpSum(s2);
        if (lane == 0) { g_esrc[d * MTOT + m] = s1; g_edst[d * MTOT + m] = s2; }
    }
}

// ---------------- softmax over j; emits single fp16 alpha ----------------
__global__ void softmax_kernel() {
    int bid = blockIdx.x;
    int b = bid >> 10;
    int i = bid & 1023;
    int t = threadIdx.x;
    int lane = t & 31, wid = t >> 5;

    __shared__ float s_esrc[4];
    __shared__ float sred[8];
    __shared__ float sbcast;

    if (t < 4) s_esrc[t] = g_esrc[t * MTOT + bid];
    __syncthreads();

    unsigned mword = *(const unsigned*)(g_Apack + (size_t)i * NN + 4 * t);

    const float NEGINF = -CUDART_INF_F;
    float ev[4];
    float lmax = NEGINF;
    #pragma unroll
    for (int e = 0; e < 4; e++) {
        unsigned m = (mword >> (8 * e)) & 0xFu;
        float val = NEGINF;
        if (m) {
            int ds = 31 - __clz(m);
            float v = s_esrc[ds] + g_edst[ds * MTOT + b * NN + 4 * t + e];
            val = v > 0.f ? v : 0.01f * v;
        }
        ev[e] = val;
        lmax = fmaxf(lmax, val);
    }
    #pragma unroll
    for (int o = 16; o; o >>= 1) lmax = fmaxf(lmax, __shfl_xor_sync(0xffffffffu, lmax, o));
    if (lane == 0) sred[wid] = lmax;
    __syncthreads();
    if (t == 0) {
        float v = sred[0];
        #pragma unroll
        for (int w = 1; w < 8; w++) v = fmaxf(v, sred[w]);
        sbcast = v;
    }
    __syncthreads();
    float rmax = sbcast;
    __syncthreads();

    float ex[4];
    float lsum = 0.f;
    #pragma unroll
    for (int e = 0; e < 4; e++) {
        float val = ev[e];
        float xx = (val == NEGINF) ? 0.f : __expf(val - rmax);
        ex[e] = xx;
        lsum += xx;
    }
    lsum = warpSum(lsum);
    if (lane == 0) sred[wid] = lsum;
    __syncthreads();
    if (t == 0) {
        float v = 0.f;
        #pragma unroll
        for (int w = 0; w < 8; w++) v += sred[w];
        sbcast = 1.f / v;
    }
    __syncthreads();
    float inv = sbcast;

    unsigned short hv[4];
    #pragma unroll
    for (int e = 0; e < 4; e++)
        hv[e] = __half_as_ushort(__float2half_rn(ex[e] * inv));
    uint2 hp = make_uint2((unsigned)hv[0] | ((unsigned)hv[1] << 16),
                          (unsigned)hv[2] | ((unsigned)hv[3] << 16));
    *(uint2*)&g_al[(size_t)bid * NN + 4 * t] = hp;
}

// ---------------- proj GEMM: Yt[d][b][o][j] = sum_f wt[o][d*256+f] * xh[b][j][f] ----------------
// CTA M=64 (o) x N=128 (j), K=256 (8 chunks of 32). 8 warps 4M x 2N: warp m16 x n64.
// smem stage: A(64x80)=5120 | B(128x80)=10240 -> 15360; double buffered.
#define AP_BYTES  (64 * 80)
#define BP_BYTES  (128 * 80)
#define STP_BYTES (AP_BYTES + BP_BYTES)
#define GSP       (2 * STP_BYTES)

__global__ void __launch_bounds__(256, 2) proj_gemm(void) {
    extern __shared__ __align__(16) char smem[];
    uint32_t sbase = smem_u32(smem);

    int t = threadIdx.x, lane = t & 31, wid = t >> 5;
    int otile = blockIdx.x, jtile = blockIdx.y, z = blockIdx.z;
    int d = z >> 3, b = z & 7;
    int o0 = otile * 64;
    int j0 = jtile * 128;

    const __half* a_p = g_wt + (size_t)o0 * 1024 + d * 256;      // row stride 1024
    const __half* b_p = g_xh + ((size_t)(b * NN) + j0) * FIN;    // row stride 256

    int ra = t >> 2, cha = t & 3;
    uint32_t soA = (uint32_t)(ra * 80 + cha * 16);
    uint32_t soB1 = soA;
    uint32_t soB2 = (uint32_t)((64 + ra) * 80 + cha * 16);

    int m_w = (wid >> 1) * 16;
    int n_w = (wid & 1) * 64;

    float acc[8][4] = {};

    auto issue = [&](int stage, int kc) {
        uint32_t st = sbase + stage * STP_BYTES;
        CP16(st + soA, a_p + (size_t)ra * 1024 + kc * 32 + cha * 8);
        CP16(st + AP_BYTES + soB1, b_p + (size_t)ra * FIN + kc * 32 + cha * 8);
        CP16(st + AP_BYTES + soB2, b_p + (size_t)(64 + ra) * FIN + kc * 32 + cha * 8);
    };

    issue(0, 0);
    CP_COMMIT();
    issue(1, 1);
    CP_COMMIT();

    #pragma unroll 1
    for (int kc = 0; kc < 8; kc++) {
        int s = kc & 1;
        if (kc == 7) CP_WAIT0(); else CP_WAIT1();
        __syncthreads();

        uint32_t uA = sbase + s * STP_BYTES;
        uint32_t uB = uA + AP_BYTES;

        #pragma unroll
        for (int s16 = 0; s16 < 2; s16++) {
            uint32_t ah[4];
            {
                uint32_t off = (uint32_t)((m_w + (lane & 15)) * 80 +
                                          s16 * 32 + (lane >> 4) * 16);
                LDSM_X4(ah[0], ah[1], ah[2], ah[3], uA + off);
            }
            #pragma unroll
            for (int p = 0; p < 4; p++) {
                uint32_t off = (uint32_t)((n_w + p * 16 + (lane & 15)) * 80 +
                                          s16 * 32 + (lane >> 4) * 16);
                uint32_t bh[4];
                LDSM_X4(bh[0], bh[1], bh[2], bh[3], uB + off);
                mma16816(acc[2 * p],     ah, bh[0], bh[2]);
                mma16816(acc[2 * p + 1], ah, bh[1], bh[3]);
            }
        }
        __syncthreads();
        if (kc + 2 < 8) {
            issue(s, kc + 2);
            CP_COMMIT();
        }
    }

    // epilogue: Yt fp16 store, row = o, col = j
    #pragma unroll
    for (int ni = 0; ni < 8; ni++) {
        int col = n_w + ni * 8 + (lane & 3) * 2;
        #pragma unroll
        for (int hh = 0; hh < 2; hh++) {
            int row = m_w + (lane >> 2) + hh * 8;
            unsigned short h0 = __half_as_ushort(__float2half_rn(acc[ni][hh * 2 + 0]));
            unsigned short h1 = __half_as_ushort(__float2half_rn(acc[ni][hh * 2 + 1]));
            unsigned hp = ((unsigned)h1 << 16) | h0;
            size_t yoff = ((size_t)z * OUTD + o0 + row) * NN + j0 + col;
            *(unsigned*)&g_yt[yoff] = hp;
        }
    }
}

// ---------------- main GEMM: out[b][i][o] = 0.5 * sum_d sum_j mask_d(alpha)[i,j] * Yt[d][b][o][j] ----------------
// CTA M=64 (i) x N=128 (o), K=1024 (32 chunks). 8 warps 4M x 2N: warp m16 x n64, acc[8][4].
// All 4 directions accumulate into ONE acc; A fragment (alpha) shared, masked per d.
// smem stage: A(64x80)=5120 | B[4](128x80 each)=40960 | mask(64x16)=1024 -> 47104.
#define AM_BYTES  (64 * 80)              // 5120
#define BM_BYTES  (128 * 80)             // 10240
#define MKM_OFF   (AM_BYTES + 4 * BM_BYTES)   // 46080
#define STM_BYTES (MKM_OFF + 64 * 16)    // 47104
#define GSM       (2 * STM_BYTES)        // 94208

__global__ void __launch_bounds__(256, 2) main_gemm(float* __restrict__ out) {
    extern __shared__ __align__(16) char smem[];
    uint32_t sbase = smem_u32(smem);

    int t = threadIdx.x, lane = t & 31, wid = t >> 5;
    int itile = blockIdx.x, otile = blockIdx.y, b = blockIdx.z;
    int i0 = itile * 64;
    int o0 = otile * 128;

    const __half* a_p = g_al + ((size_t)(b * NN) + i0) * NN;     // row stride 1024

    int ra = t >> 2, cha = t & 3;
    uint32_t soA = (uint32_t)(ra * 80 + cha * 16);
    uint32_t soB2 = (uint32_t)((64 + ra) * 80 + cha * 16);

    int m_w = (wid >> 1) * 16;
    int n_w = (wid & 1) * 64;

    float acc[8][4] = {};

    auto issue = [&](int stage, int kc) {
        uint32_t st = sbase + stage * STM_BYTES;
        CP16(st + soA, a_p + (size_t)ra * NN + kc * 32 + cha * 8);
        #pragma unroll
        for (int d = 0; d < 4; d++) {
            const __half* bp = g_yt + ((size_t)(d * BB + b) * OUTD + o0) * NN;
            CP16(st + AM_BYTES + d * BM_BYTES + soA,
                 bp + (size_t)ra * NN + kc * 32 + cha * 8);
            CP16(st + AM_BYTES + d * BM_BYTES + soB2,
                 bp + (size_t)(64 + ra) * NN + kc * 32 + cha * 8);
        }
        if (t < 64)
            CP16(st + MKM_OFF + t * 16, (const char*)&g_Abits[(size_t)(i0 + t) * 32 + kc]);
    };

    issue(0, 0);
    CP_COMMIT();
    issue(1, 1);
    CP_COMMIT();

    #pragma unroll 1
    for (int kc = 0; kc < 32; kc++) {
        int s = kc & 1;
        if (kc == 31) CP_WAIT0(); else CP_WAIT1();
        __syncthreads();

        uint32_t uA = sbase + s * STM_BYTES;
        uint32_t uB = uA + AM_BYTES;
        const uint4* mk = (const uint4*)(smem + s * STM_BYTES + MKM_OFF);

        int rr = m_w + (lane >> 2);
        uint4 w0 = mk[rr];
        uint4 w1 = mk[rr + 8];

        #pragma unroll
        for (int s16 = 0; s16 < 2; s16++) {
            uint32_t ah[4];
            {
                uint32_t off = (uint32_t)((m_w + (lane & 15)) * 80 +
                                          s16 * 32 + (lane >> 4) * 16);
                LDSM_X4(ah[0], ah[1], ah[2], ah[3], uA + off);
            }
            int sh = s16 * 16 + (lane & 3) * 2;
            #pragma unroll
            for (int d = 0; d < 4; d++) {
                unsigned wd0 = (&w0.x)[d];
                unsigned wd1 = (&w1.x)[d];
                uint32_t m0 = expand2((wd0 >> sh) & 3u);
                uint32_t m1 = expand2((wd1 >> sh) & 3u);
                uint32_t m2 = expand2((wd0 >> (sh + 8)) & 3u);
                uint32_t m3 = expand2((wd1 >> (sh + 8)) & 3u);
                uint32_t amh[4] = {ah[0] & m0, ah[1] & m1, ah[2] & m2, ah[3] & m3};
                #pragma unroll
                for (int p = 0; p < 4; p++) {
                    uint32_t off = (uint32_t)((n_w + p * 16 + (lane & 15)) * 80 +
                                              s16 * 32 + (lane >> 4) * 16);
                    uint32_t bh[4];
                    LDSM_X4(bh[0], bh[1], bh[2], bh[3], uB + d * BM_BYTES + off);
                    mma16816(acc[2 * p],     amh, bh[0], bh[2]);
                    mma16816(acc[2 * p + 1], amh, bh[1], bh[3]);
                }
            }
        }
        __syncthreads();
        if (kc + 2 < 32) {
            issue(s, kc + 2);
            CP_COMMIT();
        }
    }

    // ---- epilogue: fp32 out, scaled 0.5 ----
    #pragma unroll
    for (int ni = 0; ni < 8; ni++) {
        int col = n_w + ni * 8 + (lane & 3) * 2;
        #pragma unroll
        for (int hh = 0; hh < 2; hh++) {
            int row = m_w + (lane >> 2) + hh * 8;
            size_t ooff = ((size_t)(b * NN) + i0 + row) * 256 + o0 + col;
            float2 v = make_float2(0.5f * acc[ni][hh * 2 + 0],
                                   0.5f * acc[ni][hh * 2 + 1]);
            *(float2*)&out[ooff] = v;
        }
    }
}

// ---------------- launch ----------------
extern "C" void kernel_launch(void* const* d_in, const int* in_sizes, int n_in,
                              void* d_out, int out_size) {
    const float* x  = (const float*)d_in[0];
    const int*   AU = (const int*)d_in[1];
    const int*   AD = (const int*)d_in[2];
    const int*   AR = (const int*)d_in[3];
    const int*   AL = (const int*)d_in[4];
    const float* W  = (const float*)d_in[5];
    const float* a  = (const float*)d_in[6];
    float* out = (float*)d_out;

    cudaFuncSetAttribute(proj_gemm, cudaFuncAttributeMaxDynamicSharedMemorySize, GSP);
    cudaFuncSetAttribute(main_gemm, cudaFuncAttributeMaxDynamicSharedMemorySize, GSM);

    prep_kernel<<<DD * FIN, 256>>>(W, a);
    adj_kernel<<<(NN * 32) / 256, 256>>>(AU, AD, AR, AL);
    cast_kernel<<<(MTOT * FIN / 4) / 256, 256>>>(x);
    proj_gemm<<<dim3(4, 8, 32), 256, GSP>>>();
    edge_kernel<<<MTOT / 8, 256>>>(x);
    softmax_kernel<<<MTOT, 256>>>();
    main_gemm<<<dim3(16, 2, BB), 256, GSM>>>(out);
}

// round 15
// speedup vs baseline: 1.1444x; 1.1444x over previous
#include <cuda_runtime.h>
#include <cuda_fp16.h>
#include <math_constants.h>
#include <cstdint>

// Problem constants
#define BB   8
#define NN   1024
#define FIN  256
#define OUTD 256
#define DD   4
#define MTOT (BB * NN)   // 8192

// ---------------- scratch (static device globals; no dynamic alloc) ----------------
__device__ float g_wsrc[DD * FIN];
__device__ float g_wdst[DD * FIN];
__device__ float g_esrc[DD * MTOT];
__device__ float g_edst[DD * MTOT];
__device__ __align__(16) unsigned char g_Apack[NN * NN];              // 1 MB
__device__ __align__(16) uint4 g_Abits[NN * 32];                      // 0.5 MB bit-planes
__device__ __align__(16) __half g_al[(size_t)MTOT * NN];              // 16 MB alpha (fp16)
__device__ __align__(16) __half g_xt[BB * FIN * NN];                  // 4 MB  [b][f][j]
__device__ __align__(16) __half g_z[(size_t)MTOT * 1024];             // 16 MB [b][i][d*256+f]
__device__ __align__(16) __half g_wt[OUTD * 1024];                    // 0.5 MB [o][d*256+f]

// ---------------- helpers ----------------
__device__ __forceinline__ uint32_t smem_u32(const void* p) {
    uint32_t a;
    asm("{ .reg .u64 t; cvta.to.shared.u64 t, %1; cvt.u32.u64 %0, t; }" : "=r"(a) : "l"(p));
    return a;
}
__device__ __forceinline__ float warpSum(float v) {
    #pragma unroll
    for (int o = 16; o; o >>= 1) v += __shfl_xor_sync(0xffffffffu, v, o);
    return v;
}
// expand 2 adjacency bits -> per-half 0xFFFF masks
__device__ __forceinline__ uint32_t expand2(uint32_t b) {
    return (0xFFFFu & (0u - (b & 1u))) | (0xFFFF0000u & (0u - (b >> 1)));
}

#define LDSM_X4(r0, r1, r2, r3, addr)                                           \
    asm volatile("ldmatrix.sync.aligned.m8n8.x4.shared.b16 {%0,%1,%2,%3}, [%4];"\
                 : "=r"(r0), "=r"(r1), "=r"(r2), "=r"(r3) : "r"(addr))

#define CP16(dst, src)                                                          \
    asm volatile("cp.async.cg.shared.global [%0], [%1], 16;"                    \
                 :: "r"(dst), "l"(src))
#define CP_COMMIT() asm volatile("cp.async.commit_group;" ::: "memory")
#define CP_WAIT1()  asm volatile("cp.async.wait_group 1;" ::: "memory")
#define CP_WAIT0()  asm volatile("cp.async.wait_group 0;" ::: "memory")

__device__ __forceinline__ void mma16816(float c[4], const uint32_t a[4],
                                         uint32_t b0, uint32_t b1) {
    asm volatile(
        "mma.sync.aligned.m16n8k16.row.col.f32.f16.f16.f32 "
        "{%0,%1,%2,%3}, {%4,%5,%6,%7}, {%8,%9}, {%0,%1,%2,%3};"
        : "+f"(c[0]), "+f"(c[1]), "+f"(c[2]), "+f"(c[3])
        : "r"(a[0]), "r"(a[1]), "r"(a[2]), "r"(a[3]), "r"(b0), "r"(b1));
}

// ---------------- prep: w_src/w_dst (head 1) + Wt = transposed fp16 Wsum ----------------
__global__ void prep_kernel(const float* __restrict__ W, const float* __restrict__ a) {
    int d = blockIdx.x >> 8;
    int f = blockIdx.x & 255;
    int o = threadIdx.x;

    float w0 = W[((size_t)(d * 2 + 0) * FIN + f) * OUTD + o];
    float w1 = W[((size_t)(d * 2 + 1) * FIN + f) * OUTD + o];
    float wsum = w0 + w1;
    size_t wo = (size_t)o * 1024 + d * 256 + f;   // [o][d*256+f]
    g_wt[wo] = __float2half_rn(wsum);

    float a_s = a[(d * 2 + 1) * (2 * OUTD) + o];
    float a_d = a[(d * 2 + 1) * (2 * OUTD) + OUTD + o];
    float s1 = warpSum(w1 * a_s);
    float s2 = warpSum(w1 * a_d);
    __shared__ float r1[8], r2[8];
    int lane = threadIdx.x & 31, wid = threadIdx.x >> 5;
    if (lane == 0) { r1[wid] = s1; r2[wid] = s2; }
    __syncthreads();
    if (threadIdx.x == 0) {
        float t1 = 0.f, t2 = 0.f;
        #pragma unroll
        for (int w = 0; w < 8; w++) { t1 += r1[w]; t2 += r2[w]; }
        g_wsrc[d * FIN + f] = t1;
        g_wdst[d * FIN + f] = t2;
    }
}

// ---------------- fused adjacency pack + bit-planes ----------------
// thread handles (i, j32): 32 columns. Writes 32 Apack bytes + one uint4 of bit-planes.
__global__ void adj_kernel(const int* __restrict__ AU, const int* __restrict__ AD,
                           const int* __restrict__ AR, const int* __restrict__ AL) {
    int idx = blockIdx.x * 256 + threadIdx.x;  // 32768 = 1024 * 32
    int i = idx >> 5, j32 = idx & 31;
    size_t base = (size_t)i * NN + j32 * 32;
    unsigned w[4] = {0, 0, 0, 0};
    unsigned* pk = (unsigned*)(g_Apack + base);
    #pragma unroll
    for (int q8 = 0; q8 < 8; q8++) {
        unsigned word = 0;
        #pragma unroll
        for (int e = 0; e < 4; e++) {
            int q = q8 * 4 + e;
            unsigned m = (AU[base + q] != 0 ? 1u : 0u) | (AD[base + q] != 0 ? 2u : 0u) |
                         (AR[base + q] != 0 ? 4u : 0u) | (AL[base + q] != 0 ? 8u : 0u);
            word |= m << (8 * e);
            #pragma unroll
            for (int d = 0; d < 4; d++)
                w[d] |= ((m >> d) & 1u) << q;
        }
        pk[q8] = word;
    }
    g_Abits[idx] = make_uint4(w[0], w[1], w[2], w[3]);
}

// ---------------- x transpose + fp16: Xt[b][f][j] ----------------
__global__ void xt_kernel(const float* __restrict__ x) {
    __shared__ float tile[32][33];
    int j0 = blockIdx.x * 32, f0 = blockIdx.y * 32, b = blockIdx.z;
    int tx = threadIdx.x, ty = threadIdx.y;
    #pragma unroll
    for (int r = 0; r < 4; r++)
        tile[ty + 8 * r][tx] = x[((size_t)(b * NN) + j0 + ty + 8 * r) * FIN + f0 + tx];
    __syncthreads();
    #pragma unroll
    for (int r = 0; r < 4; r++) {
        int f = f0 + ty + 8 * r;
        int j = j0 + tx;
        float v = tile[tx][ty + 8 * r];
        g_xt[((size_t)(b * FIN) + f) * NN + j] = __float2half_rn(v);
    }
}

// ---------------- e_src/e_dst: one warp per m, all 4 directions ----------------
__global__ void edge_kernel(const float* __restrict__ x) {
    int wid = threadIdx.x >> 5, lane = threadIdx.x & 31;
    int m = blockIdx.x * 8 + wid;
    const float* xr = x + (size_t)m * FIN;
    float xv[8];
    #pragma unroll
    for (int it = 0; it < 8; it++) xv[it] = xr[lane + 32 * it];
    #pragma unroll
    for (int d = 0; d < DD; d++) {
        float s1 = 0.f, s2 = 0.f;
        #pragma unroll
        for (int it = 0; it < 8; it++) {
            int k = lane + 32 * it;
            s1 += xv[it] * g_wsrc[d * FIN + k];
            s2 += xv[it] * g_wdst[d * FIN + k];
        }
        s1 = warpSum(s1);
        s2 = warpSum(s2);
        if (lane == 0) { g_esrc[d * MTOT + m] = s1; g_edst[d * MTOT + m] = s2; }
    }
}

// ---------------- softmax over j; emits single fp16 alpha ----------------
__global__ void softmax_kernel() {
    int bid = blockIdx.x;
    int b = bid >> 10;
    int i = bid & 1023;
    int t = threadIdx.x;
    int lane = t & 31, wid = t >> 5;

    __shared__ float s_esrc[4];
    __shared__ float sred[8];
    __shared__ float sbcast;

    if (t < 4) s_esrc[t] = g_esrc[t * MTOT + bid];
    __syncthreads();

    unsigned mword = *(const unsigned*)(g_Apack + (size_t)i * NN + 4 * t);

    const float NEGINF = -CUDART_INF_F;
    float ev[4];
    float lmax = NEGINF;
    #pragma unroll
    for (int e = 0; e < 4; e++) {
        unsigned m = (mword >> (8 * e)) & 0xFu;
        float val = NEGINF;
        if (m) {
            int ds = 31 - __clz(m);
            float v = s_esrc[ds] + g_edst[ds * MTOT + b * NN + 4 * t + e];
            val = v > 0.f ? v : 0.01f * v;
        }
        ev[e] = val;
        lmax = fmaxf(lmax, val);
    }
    #pragma unroll
    for (int o = 16; o; o >>= 1) lmax = fmaxf(lmax, __shfl_xor_sync(0xffffffffu, lmax, o));
    if (lane == 0) sred[wid] = lmax;
    __syncthreads();
    if (t == 0) {
        float v = sred[0];
        #pragma unroll
        for (int w = 1; w < 8; w++) v = fmaxf(v, sred[w]);
        sbcast = v;
    }
    __syncthreads();
    float rmax = sbcast;
    __syncthreads();

    float ex[4];
    float lsum = 0.f;
    #pragma unroll
    for (int e = 0; e < 4; e++) {
        float val = ev[e];
        float xx = (val == NEGINF) ? 0.f : __expf(val - rmax);
        ex[e] = xx;
        lsum += xx;
    }
    lsum = warpSum(lsum);
    if (lane == 0) sred[wid] = lsum;
    __syncthreads();
    if (t == 0) {
        float v = 0.f;
        #pragma unroll
        for (int w = 0; w < 8; w++) v += sred[w];
        sbcast = 1.f / v;
    }
    __syncthreads();
    float inv = sbcast;

    unsigned short hv[4];
    #pragma unroll
    for (int e = 0; e < 4; e++)
        hv[e] = __half_as_ushort(__float2half_rn(ex[e] * inv));
    uint2 hp = make_uint2((unsigned)hv[0] | ((unsigned)hv[1] << 16),
                          (unsigned)hv[2] | ((unsigned)hv[3] << 16));
    *(uint2*)&g_al[(size_t)bid * NN + 4 * t] = hp;
}

// ---------------- GEMM1: all 4 directions per CTA, in-register masking, pure fp16 ----------------
// per (b, mtile, ntile): for d in 0..3: Z_d[64 i x 128 f] = sum_j (alpha*bit_d)[i,j] * xt[f,j]
// CTA 256 thr, 8 warps (4M x 2N): warp tile m16 x n64. acc[4][8][4].
// 3-stage cp.async pipeline: one __syncthreads per chunk.
// smem stage: A(64x80) | B(128x80) | Mask(64x16B) = 16384 B; 3 stages.
#define A1_BYTES  (64 * 80)                 // 5120
#define B1_BYTES  (128 * 80)                // 10240
#define MK_OFF    (A1_BYTES + B1_BYTES)     // 15360
#define ST1_BYTES (MK_OFF + 64 * 16)        // 16384
#define GS1       (3 * ST1_BYTES)           // 49152

__global__ void __launch_bounds__(256, 1) gemm1(void) {
    extern __shared__ __align__(16) char smem[];
    uint32_t sbase = smem_u32(smem);

    int t = threadIdx.x, lane = t & 31, wid = t >> 5;
    int mtile = blockIdx.x, ntile = blockIdx.y, b = blockIdx.z;
    int i0 = mtile * 64;
    int n0 = ntile * 128;

    const __half* a_p = g_al + ((size_t)(b * NN) + i0) * NN;
    const __half* b_p = g_xt + (size_t)b * FIN * NN + (size_t)n0 * NN;

    int ra = t >> 2, cha = t & 3;            // A rows 0..63, 4 chunks
    uint32_t soA = (uint32_t)(ra * 80 + cha * 16);
    uint32_t soB2 = (uint32_t)((64 + ra) * 80 + cha * 16);

    int m_w = (wid >> 1) * 16;
    int n_w = (wid & 1) * 64;

    float acc[4][8][4] = {};

    auto issue = [&](int stage, int kc) {
        uint32_t st = sbase + stage * ST1_BYTES;
        size_t oa = (size_t)ra * NN + kc * 32 + cha * 8;
        CP16(st + soA, a_p + oa);
        CP16(st + A1_BYTES + soA,  b_p + oa);
        CP16(st + A1_BYTES + soB2, b_p + (size_t)(64 + ra) * NN + kc * 32 + cha * 8);
        if (t < 64)
            CP16(st + MK_OFF + t * 16, (const char*)&g_Abits[(size_t)(i0 + t) * 32 + kc]);
    };

    issue(0, 0);
    CP_COMMIT();
    issue(1, 1);
    CP_COMMIT();

    #pragma unroll 1
    for (int kc = 0; kc < 32; kc++) {
        int s = kc % 3;
        if (kc == 31) CP_WAIT0(); else CP_WAIT1();
        __syncthreads();   // all warps done with stage (kc-1)%3; chunk kc resident in stage s

        uint32_t uA = sbase + s * ST1_BYTES;
        uint32_t uB = uA + A1_BYTES;
        const uint4* mk = (const uint4*)(smem + s * ST1_BYTES + MK_OFF);

        int rr = m_w + (lane >> 2);
        uint4 w0 = mk[rr];
        uint4 w1 = mk[rr + 8];

        #pragma unroll
        for (int s16 = 0; s16 < 2; s16++) {
            uint32_t ah[4];
            {
                uint32_t off = (uint32_t)((m_w + (lane & 15)) * 80 +
                                          s16 * 32 + (lane >> 4) * 16);
                LDSM_X4(ah[0], ah[1], ah[2], ah[3], uA + off);
            }
            uint32_t bh[4][4];
            #pragma unroll
            for (int p = 0; p < 4; p++) {
                uint32_t off = (uint32_t)((n_w + p * 16 + (lane & 15)) * 80 +
                                          s16 * 32 + (lane >> 4) * 16);
                LDSM_X4(bh[p][0], bh[p][1], bh[p][2], bh[p][3], uB + off);
            }
            int sh = s16 * 16 + (lane & 3) * 2;
            #pragma unroll
            for (int d = 0; d < 4; d++) {
                unsigned wd0 = (&w0.x)[d];
                unsigned wd1 = (&w1.x)[d];
                uint32_t m0 = expand2((wd0 >> sh) & 3u);
                uint32_t m1 = expand2((wd1 >> sh) & 3u);
                uint32_t m2 = expand2((wd0 >> (sh + 8)) & 3u);
                uint32_t m3 = expand2((wd1 >> (sh + 8)) & 3u);
                uint32_t amh[4] = {ah[0] & m0, ah[1] & m1, ah[2] & m2, ah[3] & m3};
                #pragma unroll
                for (int p = 0; p < 4; p++) {
                    mma16816(acc[d][2 * p],     amh, bh[p][0], bh[p][2]);
                    mma16816(acc[d][2 * p + 1], amh, bh[p][1], bh[p][3]);
                }
            }
        }
        // no second barrier: stage (kc+2)%3 == (kc-1)%3, whose readers all
        // passed this iteration's top barrier already.
        if (kc + 2 < 32) {
            issue((kc + 2) % 3, kc + 2);
            CP_COMMIT();
        }
    }

    // ---- epilogue: fp16 Z stores for all 4 d ----
    #pragma unroll
    for (int d = 0; d < 4; d++) {
        #pragma unroll
        for (int ni = 0; ni < 8; ni++) {
            int col = n_w + ni * 8 + (lane & 3) * 2;
            #pragma unroll
            for (int hh = 0; hh < 2; hh++) {
                int row = m_w + (lane >> 2) + hh * 8;
                unsigned short h0 = __half_as_ushort(__float2half_rn(acc[d][ni][hh * 2 + 0]));
                unsigned short h1 = __half_as_ushort(__float2half_rn(acc[d][ni][hh * 2 + 1]));
                unsigned hp = ((unsigned)h1 << 16) | h0;
                size_t zoff = ((size_t)(b * NN) + i0 + row) * 1024 + d * 256 + n0 + col;
                *(unsigned*)&g_z[zoff] = hp;
            }
        }
    }
}

// ---------------- GEMM2: out = 0.5 * Z @ Wt^T, pure fp16, 3-stage pipeline ----------------
#define KCHUNKS     32
#define ARR2_BYTES  (128 * 80)          // 10240
#define ST2_BYTES   (2 * ARR2_BYTES)    // 20480: A | B
#define GS2         (3 * ST2_BYTES)     // 61440

__global__ void __launch_bounds__(256, 2) gemm2(float* __restrict__ out) {
    extern __shared__ __align__(16) char smem[];
    uint32_t sbase = smem_u32(smem);

    int t = threadIdx.x, lane = t & 31, wid = t >> 5;
    int mtile = blockIdx.x, ntile = blockIdx.y, b = blockIdx.z;
    int i0 = mtile * 128;
    int n0 = ntile * 128;

    const __half* a_p = g_z + ((size_t)(b * NN) + i0) * 1024;
    const __half* b_p = g_wt + (size_t)n0 * 1024;

    int r1 = t >> 2,          ch1 = t & 3;
    int r2 = (t + 256) >> 2,  ch2 = (t + 256) & 3;
    uint32_t so1 = (uint32_t)(r1 * 80 + ch1 * 16);
    uint32_t so2 = (uint32_t)(r2 * 80 + ch2 * 16);

    int m_w = (wid >> 1) * 32;
    int n_w = (wid & 1) * 64;

    float acc[2][8][4] = {};

    auto issue = [&](int stage, int k0) {
        uint32_t st = sbase + stage * ST2_BYTES;
        size_t o1 = (size_t)r1 * 1024 + k0 + ch1 * 8;
        size_t o2 = (size_t)r2 * 1024 + k0 + ch2 * 8;
        CP16(st + so1,              a_p + o1);
        CP16(st + so2,              a_p + o2);
        CP16(st + ARR2_BYTES + so1, b_p + o1);
        CP16(st + ARR2_BYTES + so2, b_p + o2);
    };

    issue(0, 0);
    CP_COMMIT();
    issue(1, 32);
    CP_COMMIT();

    #pragma unroll 1
    for (int kc = 0; kc < KCHUNKS; kc++) {
        int s = kc % 3;
        if (kc == KCHUNKS - 1) CP_WAIT0(); else CP_WAIT1();
        __syncthreads();

        uint32_t uA = sbase + s * ST2_BYTES;
        uint32_t uB = uA + ARR2_BYTES;

        #pragma unroll
        for (int s16 = 0; s16 < 2; s16++) {
            uint32_t ah[2][4];
            #pragma unroll
            for (int mi = 0; mi < 2; mi++) {
                uint32_t off = (uint32_t)((m_w + mi * 16 + (lane & 15)) * 80 +
                                          s16 * 32 + (lane >> 4) * 16);
                LDSM_X4(ah[mi][0], ah[mi][1], ah[mi][2], ah[mi][3], uA + off);
            }
            #pragma unroll
            for (int p = 0; p < 4; p++) {
                uint32_t off = (uint32_t)((n_w + p * 16 + (lane & 15)) * 80 +
                                          s16 * 32 + (lane >> 4) * 16);
                uint32_t bh[4];
                LDSM_X4(bh[0], bh[1], bh[2], bh[3], uB + off);
                #pragma unroll
                for (int mi = 0; mi < 2; mi++) {
                    mma16816(acc[mi][2 * p],     ah[mi], bh[0], bh[2]);
                    mma16816(acc[mi][2 * p + 1], ah[mi], bh[1], bh[3]);
                }
            }
        }
        if (kc + 2 < KCHUNKS) {
            issue((kc + 2) % 3, (kc + 2) * 32);
            CP_COMMIT();
        }
    }

    #pragma unroll
    for (int mi = 0; mi < 2; mi++) {
        #pragma unroll
        for (int ni = 0; ni < 8; ni++) {
            int col = n_w + ni * 8 + (lane & 3) * 2;
            #pragma unroll
            for (int hh = 0; hh < 2; hh++) {
                int row = m_w + mi * 16 + (lane >> 2) + hh * 8;
                size_t ooff = ((size_t)(b * NN) + i0 + row) * 256 + n0 + col;
                float2 v = make_float2(0.5f * acc[mi][ni][hh * 2 + 0],
                                       0.5f * acc[mi][ni][hh * 2 + 1]);
                *(float2*)&out[ooff] = v;
            }
        }
    }
}

// ---------------- launch ----------------
extern "C" void kernel_launch(void* const* d_in, const int* in_sizes, int n_in,
                              void* d_out, int out_size) {
    const float* x  = (const float*)d_in[0];
    const int*   AU = (const int*)d_in[1];
    const int*   AD = (const int*)d_in[2];
    const int*   AR = (const int*)d_in[3];
    const int*   AL = (const int*)d_in[4];
    const float* W  = (const float*)d_in[5];
    const float* a  = (const float*)d_in[6];
    float* out = (float*)d_out;

    cudaFuncSetAttribute(gemm1, cudaFuncAttributeMaxDynamicSharedMemorySize, GS1);
    cudaFuncSetAttribute(gemm2, cudaFuncAttributeMaxDynamicSharedMemorySize, GS2);

    prep_kernel<<<DD * FIN, 256>>>(W, a);
    adj_kernel<<<(NN * 32) / 256, 256>>>(AU, AD, AR, AL);
    xt_kernel<<<dim3(NN / 32, FIN / 32, BB), dim3(32, 8)>>>(x);
    edge_kernel<<<MTOT / 8, 256>>>(x);
    softmax_kernel<<<MTOT, 256>>>();
    gemm1<<<dim3(16, 2, BB), 256, GS1>>>();
    gemm2<<<dim3(8, 2, BB), 256, GS2>>>(out);
}